// round 3
// baseline (speedup 1.0000x reference)
#include <cuda_runtime.h>
#include <cuda_bf16.h>
#include <math.h>

#define HDIM 128
#define MAXM 1000
#define MAXJ 5000
#define MAXN 200000
#define TOPS 16
#define PAD  20   // 20 floats = 80B row stride; 16B-aligned for float4, breaks worst bank conflicts

// scratch (no cudaMalloc allowed)
__device__ float g_g[HDIM];              // x_graph @ W0[:2H] + b0
__device__ float g_A[MAXM * HDIM];       // g + x_m @ W0[2H:3H]
__device__ float g_B[MAXJ * HDIM];       // x_job @ W0[3H:4H]
__device__ float g_scores[MAXN];

// ---------------------------------------------------------------------------
// Kernel 0: g[h] = b0[h] + sum_{k<2H} x_graph[k] * W0[k][h]
// ---------------------------------------------------------------------------
__global__ void kern_g(const float* __restrict__ x_graph,
                       const float* __restrict__ W0,
                       const float* __restrict__ b0)
{
    __shared__ float xs[2 * HDIM];
    int h = threadIdx.x;           // 0..127
    xs[h] = x_graph[h];
    xs[h + HDIM] = x_graph[h + HDIM];
    __syncthreads();
    float acc = b0[h];
    #pragma unroll 8
    for (int k = 0; k < 2 * HDIM; ++k)
        acc = fmaf(xs[k], W0[k * HDIM + h], acc);
    g_g[h] = acc;
}

// ---------------------------------------------------------------------------
// Kernel 1: A[m][h] = g[h] + sum_k x_m[m][k]*W0[2H+k][h]
//           B[j][h] =        sum_k x_job[j][k]*W0[3H+k][h]
// one block per row
// ---------------------------------------------------------------------------
__global__ void kern_AB(const float* __restrict__ x_m,
                        const float* __restrict__ x_job,
                        const float* __restrict__ W0,
                        int M, int J)
{
    __shared__ float xs[HDIM];
    int h = threadIdx.x;
    int r = blockIdx.x;
    const float* src;
    const float* w;
    float* dst;
    float acc;
    if (r < M) {
        src = x_m + (size_t)r * HDIM;
        w   = W0 + (size_t)(2 * HDIM) * HDIM;
        dst = g_A + (size_t)r * HDIM;
        acc = g_g[h];
    } else {
        int j = r - M;
        src = x_job + (size_t)j * HDIM;
        w   = W0 + (size_t)(3 * HDIM) * HDIM;
        dst = g_B + (size_t)j * HDIM;
        acc = 0.0f;
    }
    xs[h] = src[h];
    __syncthreads();
    #pragma unroll 8
    for (int k = 0; k < HDIM; ++k)
        acc = fmaf(xs[k], w[k * HDIM + h], acc);
    dst[h] = acc;
}

// ---------------------------------------------------------------------------
// Kernel 2: main MLP. Each block: 16 ops, 128 threads (thread = output dim h).
//   h0[t][k] = relu(A[m_t][k] + B[j_t][k])      (staged in smem, [k][t] pad-20)
//   h1[t][h] = relu(b1[h] + sum_k h0[t][k]*W1[k][h])
//   s[t]     = b2 + sum_h h1[t][h]*W2[h]
// ---------------------------------------------------------------------------
__global__ void __launch_bounds__(HDIM)
kern_mlp(const int* __restrict__ m_ids,
         const int* __restrict__ job_idx,
         const float* __restrict__ W1,
         const float* __restrict__ b1,
         const float* __restrict__ W2,
         const float* __restrict__ b2,
         int n)
{
    __shared__ float4 h0s4[HDIM * (PAD / 4)];       // 128 rows x 20 floats
    __shared__ float wpart[4 * TOPS];
    float* h0s = reinterpret_cast<float*>(h0s4);

    int h = threadIdx.x;
    int base = blockIdx.x * TOPS;

    // ---- stage 1: gather + relu ----
    #pragma unroll
    for (int t = 0; t < TOPS; ++t) {
        int op = base + t;
        float v = 0.0f;
        if (op < n) {
            int m = m_ids[op];
            int j = job_idx[op];
            v = g_A[m * HDIM + h] + g_B[j * HDIM + h];
            v = fmaxf(v, 0.0f);
        }
        h0s[h * PAD + t] = v;
    }
    __syncthreads();

    // ---- stage 2: h0 @ W1 ----
    float acc[TOPS];
    float bb = b1[h];
    #pragma unroll
    for (int t = 0; t < TOPS; ++t) acc[t] = bb;

    #pragma unroll 4
    for (int k = 0; k < HDIM; ++k) {
        float w = W1[k * HDIM + h];
        const float4* p = reinterpret_cast<const float4*>(&h0s[k * PAD]);
        float4 a0 = p[0], a1 = p[1], a2 = p[2], a3 = p[3];
        acc[0]  = fmaf(a0.x, w, acc[0]);
        acc[1]  = fmaf(a0.y, w, acc[1]);
        acc[2]  = fmaf(a0.z, w, acc[2]);
        acc[3]  = fmaf(a0.w, w, acc[3]);
        acc[4]  = fmaf(a1.x, w, acc[4]);
        acc[5]  = fmaf(a1.y, w, acc[5]);
        acc[6]  = fmaf(a1.z, w, acc[6]);
        acc[7]  = fmaf(a1.w, w, acc[7]);
        acc[8]  = fmaf(a2.x, w, acc[8]);
        acc[9]  = fmaf(a2.y, w, acc[9]);
        acc[10] = fmaf(a2.z, w, acc[10]);
        acc[11] = fmaf(a2.w, w, acc[11]);
        acc[12] = fmaf(a3.x, w, acc[12]);
        acc[13] = fmaf(a3.y, w, acc[13]);
        acc[14] = fmaf(a3.z, w, acc[14]);
        acc[15] = fmaf(a3.w, w, acc[15]);
    }

    // ---- stage 3: relu, * W2[h], block-reduce over h ----
    float w2 = W2[h];
    int lane = h & 31;
    int warp = h >> 5;
    unsigned mask = 0xffffffffu;
    #pragma unroll
    for (int t = 0; t < TOPS; ++t) {
        float v = fmaxf(acc[t], 0.0f) * w2;
        v += __shfl_down_sync(mask, v, 16);
        v += __shfl_down_sync(mask, v, 8);
        v += __shfl_down_sync(mask, v, 4);
        v += __shfl_down_sync(mask, v, 2);
        v += __shfl_down_sync(mask, v, 1);
        if (lane == 0) wpart[warp * TOPS + t] = v;
    }
    __syncthreads();
    if (h < TOPS) {
        int op = base + h;
        if (op < n) {
            float s = wpart[0 * TOPS + h] + wpart[1 * TOPS + h] +
                      wpart[2 * TOPS + h] + wpart[3 * TOPS + h] + b2[0];
            g_scores[op] = s;
        }
    }
}

// ---------------------------------------------------------------------------
// Kernel 3: softmax stats. One block, deterministic tree reductions.
//   t_i = s_i - max;  Z = sum e^t;  S1 = sum t*e^t
//   out = [idx, 1/Z, -logZ, logZ - S1/Z]
// ---------------------------------------------------------------------------
#define RTH 1024
__global__ void __launch_bounds__(RTH)
kern_reduce(int n, float* __restrict__ out)
{
    __shared__ float  sv[RTH];
    __shared__ int    si[RTH];
    __shared__ double sz[RTH];
    __shared__ double ss[RTH];

    int tid = threadIdx.x;

    // phase A: max + first-occurrence argmax
    float best = -INFINITY;
    int bi = 0x7fffffff;
    for (int i = tid; i < n; i += RTH) {
        float v = g_scores[i];
        if (v > best) { best = v; bi = i; }
    }
    sv[tid] = best; si[tid] = bi;
    __syncthreads();
    for (int s = RTH / 2; s > 0; s >>= 1) {
        if (tid < s) {
            float vo = sv[tid + s]; int io = si[tid + s];
            if (vo > sv[tid] || (vo == sv[tid] && io < si[tid])) {
                sv[tid] = vo; si[tid] = io;
            }
        }
        __syncthreads();
    }
    float mx = sv[0];
    int idx = si[0];
    __syncthreads();

    // phase B: Z and S1 (double partials, fixed-order tree)
    double z = 0.0, s1 = 0.0;
    for (int i = tid; i < n; i += RTH) {
        float t = g_scores[i] - mx;
        float e = expf(t);
        z  += (double)e;
        s1 += (double)t * (double)e;
    }
    sz[tid] = z; ss[tid] = s1;
    __syncthreads();
    for (int s = RTH / 2; s > 0; s >>= 1) {
        if (tid < s) { sz[tid] += sz[tid + s]; ss[tid] += ss[tid + s]; }
        __syncthreads();
    }
    if (tid == 0) {
        double Z = sz[0], S1 = ss[0];
        double logZ = log(Z);
        out[0] = (float)idx;
        out[1] = (float)(1.0 / Z);
        out[2] = (float)(-logZ);
        out[3] = (float)(logZ - S1 / Z);
    }
}

// ---------------------------------------------------------------------------
extern "C" void kernel_launch(void* const* d_in, const int* in_sizes, int n_in,
                              void* d_out, int out_size)
{
    const float* x_graph = (const float*)d_in[0];
    const float* x_m     = (const float*)d_in[1];
    const float* x_job   = (const float*)d_in[2];
    const int*   m_ids   = (const int*)  d_in[3];
    const int*   job_idx = (const int*)  d_in[4];
    const float* W0      = (const float*)d_in[5];
    const float* b0      = (const float*)d_in[6];
    const float* W1      = (const float*)d_in[7];
    const float* b1      = (const float*)d_in[8];
    const float* W2      = (const float*)d_in[9];
    const float* b2      = (const float*)d_in[10];

    int n = in_sizes[3];
    int M = in_sizes[1] / HDIM;
    int J = in_sizes[2] / HDIM;

    kern_g<<<1, HDIM>>>(x_graph, W0, b0);
    kern_AB<<<M + J, HDIM>>>(x_m, x_job, W0, M, J);
    kern_mlp<<<(n + TOPS - 1) / TOPS, HDIM>>>(m_ids, job_idx, W1, b1, W2, b2, n);
    kern_reduce<<<1, RTH>>>(n, (float*)d_out);
}

// round 4
// speedup vs baseline: 1.8469x; 1.8469x over previous
#include <cuda_runtime.h>
#include <cuda_bf16.h>
#include <math.h>

#define HDIM 128
#define MAXM 1000
#define MAXJ 5000
#define MAXN 200000
#define TOPS 16
#define PAD  20   // 20 floats = 80B row stride; 16B-aligned for 128b loads

#define RBLKS 256
#define RTH   512

// scratch (no cudaMalloc allowed)
__device__ float  g_g[HDIM];
__device__ float  g_A[MAXM * HDIM];
__device__ float  g_B[MAXJ * HDIM];
__device__ float  g_scores[MAXN];
__device__ float  g_pmax[RBLKS];
__device__ int    g_pidx[RBLKS];
__device__ double g_pZ[RBLKS];
__device__ double g_pS1[RBLKS];

// ---- packed f32x2 helpers (sm_103a FFMA2 — ptxas never auto-generates) ----
__device__ __forceinline__ unsigned long long pack2(float lo, float hi) {
    unsigned long long r;
    asm("mov.b64 %0, {%1, %2};" : "=l"(r) : "f"(lo), "f"(hi));
    return r;
}
__device__ __forceinline__ void unpack2(unsigned long long v, float& lo, float& hi) {
    asm("mov.b64 {%0, %1}, %2;" : "=f"(lo), "=f"(hi) : "l"(v));
}
__device__ __forceinline__ void ffma2(unsigned long long& d,
                                      unsigned long long a,
                                      unsigned long long b) {
    asm("fma.rn.f32x2 %0, %1, %2, %3;" : "=l"(d) : "l"(a), "l"(b), "l"(d));
}

// ---------------------------------------------------------------------------
// Kernel 0: g[h] = b0[h] + sum_{k<2H} x_graph[k] * W0[k][h]
// ---------------------------------------------------------------------------
__global__ void kern_g(const float* __restrict__ x_graph,
                       const float* __restrict__ W0,
                       const float* __restrict__ b0)
{
    __shared__ float xs[2 * HDIM];
    int h = threadIdx.x;
    xs[h] = x_graph[h];
    xs[h + HDIM] = x_graph[h + HDIM];
    __syncthreads();
    float acc = b0[h];
    #pragma unroll 8
    for (int k = 0; k < 2 * HDIM; ++k)
        acc = fmaf(xs[k], W0[k * HDIM + h], acc);
    g_g[h] = acc;
}

// ---------------------------------------------------------------------------
// Kernel 1: A[m][h] = g[h] + x_m[m] @ W0[2H:3H];  B[j][h] = x_job[j] @ W0[3H:4H]
// ---------------------------------------------------------------------------
__global__ void kern_AB(const float* __restrict__ x_m,
                        const float* __restrict__ x_job,
                        const float* __restrict__ W0,
                        int M, int J)
{
    __shared__ float xs[HDIM];
    int h = threadIdx.x;
    int r = blockIdx.x;
    const float* src;
    const float* w;
    float* dst;
    float acc;
    if (r < M) {
        src = x_m + (size_t)r * HDIM;
        w   = W0 + (size_t)(2 * HDIM) * HDIM;
        dst = g_A + (size_t)r * HDIM;
        acc = g_g[h];
    } else {
        int j = r - M;
        src = x_job + (size_t)j * HDIM;
        w   = W0 + (size_t)(3 * HDIM) * HDIM;
        dst = g_B + (size_t)j * HDIM;
        acc = 0.0f;
    }
    xs[h] = src[h];
    __syncthreads();
    #pragma unroll 8
    for (int k = 0; k < HDIM; ++k)
        acc = fmaf(xs[k], w[k * HDIM + h], acc);
    dst[h] = acc;
}

// ---------------------------------------------------------------------------
// Kernel 2: main MLP, f32x2 packed mainloop. 16 ops/block, 128 threads.
// ---------------------------------------------------------------------------
__global__ void __launch_bounds__(HDIM)
kern_mlp(const int* __restrict__ m_ids,
         const int* __restrict__ job_idx,
         const float* __restrict__ W1,
         const float* __restrict__ b1,
         const float* __restrict__ W2,
         const float* __restrict__ b2,
         int n)
{
    __shared__ float4 h0s4[HDIM * (PAD / 4)];       // 128 rows x 20 floats
    __shared__ float wpart[4 * TOPS];
    float* h0s = reinterpret_cast<float*>(h0s4);

    int h = threadIdx.x;
    int base = blockIdx.x * TOPS;

    // ---- stage 1: gather + relu ----
    #pragma unroll
    for (int t = 0; t < TOPS; ++t) {
        int op = base + t;
        float v = 0.0f;
        if (op < n) {
            int m = m_ids[op];
            int j = job_idx[op];
            v = g_A[m * HDIM + h] + g_B[j * HDIM + h];
            v = fmaxf(v, 0.0f);
        }
        h0s[h * PAD + t] = v;
    }
    __syncthreads();

    // ---- stage 2: h0 @ W1 with packed f32x2 FMAs ----
    unsigned long long acc2[TOPS / 2];
    float bb = b1[h];
    unsigned long long bb2 = pack2(bb, bb);
    #pragma unroll
    for (int i = 0; i < TOPS / 2; ++i) acc2[i] = bb2;

    #pragma unroll 4
    for (int k = 0; k < HDIM; ++k) {
        float w = W1[k * HDIM + h];
        unsigned long long wd = pack2(w, w);
        const ulonglong2* p = reinterpret_cast<const ulonglong2*>(&h0s[k * PAD]);
        ulonglong2 q0 = p[0];   // t pairs (0,1),(2,3)
        ulonglong2 q1 = p[1];   // (4,5),(6,7)
        ulonglong2 q2 = p[2];   // (8,9),(10,11)
        ulonglong2 q3 = p[3];   // (12,13),(14,15)
        ffma2(acc2[0], q0.x, wd);
        ffma2(acc2[1], q0.y, wd);
        ffma2(acc2[2], q1.x, wd);
        ffma2(acc2[3], q1.y, wd);
        ffma2(acc2[4], q2.x, wd);
        ffma2(acc2[5], q2.y, wd);
        ffma2(acc2[6], q3.x, wd);
        ffma2(acc2[7], q3.y, wd);
    }

    // ---- stage 3: relu, * W2[h], block-reduce over h ----
    float w2 = W2[h];
    int lane = h & 31;
    int warp = h >> 5;
    unsigned mask = 0xffffffffu;
    #pragma unroll
    for (int i = 0; i < TOPS / 2; ++i) {
        float lo, hi;
        unpack2(acc2[i], lo, hi);
        float vals[2] = { lo, hi };
        #pragma unroll
        for (int u = 0; u < 2; ++u) {
            int t = 2 * i + u;
            float v = fmaxf(vals[u], 0.0f) * w2;
            v += __shfl_down_sync(mask, v, 16);
            v += __shfl_down_sync(mask, v, 8);
            v += __shfl_down_sync(mask, v, 4);
            v += __shfl_down_sync(mask, v, 2);
            v += __shfl_down_sync(mask, v, 1);
            if (lane == 0) wpart[warp * TOPS + t] = v;
        }
    }
    __syncthreads();
    if (h < TOPS) {
        int op = base + h;
        if (op < n) {
            float s = wpart[0 * TOPS + h] + wpart[1 * TOPS + h] +
                      wpart[2 * TOPS + h] + wpart[3 * TOPS + h] + b2[0];
            g_scores[op] = s;
        }
    }
}

// ---------------------------------------------------------------------------
// Kernel 3a: per-block softmax partials over contiguous chunk.
//   local max/argmax (first occurrence), then Z_b, S1_b relative to local max.
// ---------------------------------------------------------------------------
__global__ void __launch_bounds__(RTH)
kern_reduce1(int n, int chunk)
{
    __shared__ float  sv[RTH];
    __shared__ int    si[RTH];
    __shared__ double sz[RTH];
    __shared__ double ss[RTH];

    int tid = threadIdx.x;
    int b = blockIdx.x;
    int start = b * chunk;
    int end = min(n, start + chunk);

    float best = -INFINITY;
    int bi = 0x7fffffff;
    for (int i = start + tid; i < end; i += RTH) {
        float v = g_scores[i];
        if (v > best) { best = v; bi = i; }
    }
    sv[tid] = best; si[tid] = bi;
    __syncthreads();
    for (int s = RTH / 2; s > 0; s >>= 1) {
        if (tid < s) {
            float vo = sv[tid + s]; int io = si[tid + s];
            if (vo > sv[tid] || (vo == sv[tid] && io < si[tid])) {
                sv[tid] = vo; si[tid] = io;
            }
        }
        __syncthreads();
    }
    float mx = sv[0];
    int idx = si[0];
    __syncthreads();

    double z = 0.0, s1 = 0.0;
    for (int i = start + tid; i < end; i += RTH) {
        float t = g_scores[i] - mx;
        float e = expf(t);
        z  += (double)e;
        s1 += (double)t * (double)e;
    }
    sz[tid] = z; ss[tid] = s1;
    __syncthreads();
    for (int s = RTH / 2; s > 0; s >>= 1) {
        if (tid < s) { sz[tid] += sz[tid + s]; ss[tid] += ss[tid + s]; }
        __syncthreads();
    }
    if (tid == 0) {
        g_pmax[b] = mx;
        g_pidx[b] = idx;
        g_pZ[b]   = sz[0];
        g_pS1[b]  = ss[0];
    }
}

// ---------------------------------------------------------------------------
// Kernel 3b: combine RBLKS partials.  Z = sum e^{m_b-mx} Z_b;
//   S1 = sum e^{m_b-mx} (S1_b + (m_b-mx) Z_b).  Fixed tree -> deterministic.
// ---------------------------------------------------------------------------
__global__ void __launch_bounds__(RBLKS)
kern_reduce2(float* __restrict__ out)
{
    __shared__ float  sv[RBLKS];
    __shared__ int    si[RBLKS];
    __shared__ double sz[RBLKS];
    __shared__ double ss[RBLKS];

    int tid = threadIdx.x;
    sv[tid] = g_pmax[tid];
    si[tid] = g_pidx[tid];
    __syncthreads();
    for (int s = RBLKS / 2; s > 0; s >>= 1) {
        if (tid < s) {
            float vo = sv[tid + s]; int io = si[tid + s];
            if (vo > sv[tid] || (vo == sv[tid] && io < si[tid])) {
                sv[tid] = vo; si[tid] = io;
            }
        }
        __syncthreads();
    }
    float mx = sv[0];
    int idx = si[0];
    __syncthreads();

    double zb = g_pZ[tid];
    double zc = 0.0, sc = 0.0;
    if (zb > 0.0) {
        double d = (double)g_pmax[tid] - (double)mx;
        double w = exp(d);
        zc = w * zb;
        sc = w * (g_pS1[tid] + d * zb);
    }
    sz[tid] = zc; ss[tid] = sc;
    __syncthreads();
    for (int s = RBLKS / 2; s > 0; s >>= 1) {
        if (tid < s) { sz[tid] += sz[tid + s]; ss[tid] += ss[tid + s]; }
        __syncthreads();
    }
    if (tid == 0) {
        double Z = sz[0], S1 = ss[0];
        double logZ = log(Z);
        out[0] = (float)idx;
        out[1] = (float)(1.0 / Z);
        out[2] = (float)(-logZ);
        out[3] = (float)(logZ - S1 / Z);
    }
}

// ---------------------------------------------------------------------------
extern "C" void kernel_launch(void* const* d_in, const int* in_sizes, int n_in,
                              void* d_out, int out_size)
{
    const float* x_graph = (const float*)d_in[0];
    const float* x_m     = (const float*)d_in[1];
    const float* x_job   = (const float*)d_in[2];
    const int*   m_ids   = (const int*)  d_in[3];
    const int*   job_idx = (const int*)  d_in[4];
    const float* W0      = (const float*)d_in[5];
    const float* b0      = (const float*)d_in[6];
    const float* W1      = (const float*)d_in[7];
    const float* b1      = (const float*)d_in[8];
    const float* W2      = (const float*)d_in[9];
    const float* b2      = (const float*)d_in[10];

    int n = in_sizes[3];
    int M = in_sizes[1] / HDIM;
    int J = in_sizes[2] / HDIM;

    int chunk = (n + RBLKS - 1) / RBLKS;

    kern_g<<<1, HDIM>>>(x_graph, W0, b0);
    kern_AB<<<M + J, HDIM>>>(x_m, x_job, W0, M, J);
    kern_mlp<<<(n + TOPS - 1) / TOPS, HDIM>>>(m_ids, job_idx, W1, b1, W2, b2, n);
    kern_reduce1<<<RBLKS, RTH>>>(n, chunk);
    kern_reduce2<<<1, RBLKS>>>((float*)d_out);
}

// round 6
// speedup vs baseline: 3.8255x; 2.0713x over previous
#include <cuda_runtime.h>
#include <cuda_bf16.h>
#include <math.h>
#include <stdint.h>

#define HDIM 128
#define MAXM 1000
#define MAXJ 5000
#define MAXN 200000
#define TILE_OPS 128

#define RBLKS 256
#define RTH   512

// ------------------------------ scratch ------------------------------------
__device__ __align__(16) float  g_g[HDIM];
__device__ __align__(16) float  g_A[MAXM * HDIM];
__device__ __align__(16) float  g_B[MAXJ * HDIM];
__device__ __align__(16) float  g_scores[MAXN];
__device__ float  g_pmax[RBLKS];
__device__ int    g_pidx[RBLKS];
__device__ double g_pZ[RBLKS];
__device__ double g_pS1[RBLKS];
// W1^T (rows = output h, cols = k), bf16 hi/lo split, blocked-SW128 layout.
__device__ __align__(16) unsigned char g_W1T[65536];

// --------------------------- helpers ---------------------------------------
__device__ __forceinline__ uint32_t smem_u32(const void* p) {
    uint32_t a;
    asm("{ .reg .u64 t; cvta.to.shared.u64 t, %1; cvt.u32.u64 %0, t; }"
        : "=r"(a) : "l"(p));
    return a;
}

// swizzled byte offset in a 128row x 128col bf16 blocked-SW128 tile
// atoms: 8 rows x 64 cols (1KB); 16 atom-rows; col-atom stride = 16KB
__device__ __forceinline__ uint32_t tile_off(int row, int col) {
    uint32_t off = (uint32_t)(((row >> 3) + ((col >> 6) << 4)) * 1024
                              + (row & 7) * 128 + (col & 63) * 2);
    return off ^ ((off >> 3) & 0x70);
}

__device__ __forceinline__ void ldsm4(uint32_t* r, uint32_t addr) {
    asm volatile("ldmatrix.sync.aligned.m8n8.x4.shared.b16 {%0,%1,%2,%3}, [%4];"
                 : "=r"(r[0]), "=r"(r[1]), "=r"(r[2]), "=r"(r[3]) : "r"(addr));
}
__device__ __forceinline__ void mma_bf16(float* d, const uint32_t* a,
                                         uint32_t b0, uint32_t b1) {
    asm volatile("mma.sync.aligned.m16n8k16.row.col.f32.bf16.bf16.f32 "
                 "{%0,%1,%2,%3}, {%4,%5,%6,%7}, {%8,%9}, {%0,%1,%2,%3};"
                 : "+f"(d[0]), "+f"(d[1]), "+f"(d[2]), "+f"(d[3])
                 : "r"(a[0]), "r"(a[1]), "r"(a[2]), "r"(a[3]), "r"(b0), "r"(b1));
}

// ---------------------------------------------------------------------------
// Kernel 0: g[h] = b0[h] + x_graph @ W0[:2H]
// ---------------------------------------------------------------------------
__global__ void kern_g(const float* __restrict__ x_graph,
                       const float* __restrict__ W0,
                       const float* __restrict__ b0)
{
    __shared__ float xs[2 * HDIM];
    int h = threadIdx.x;
    xs[h] = x_graph[h];
    xs[h + HDIM] = x_graph[h + HDIM];
    __syncthreads();
    float acc = b0[h];
    #pragma unroll 8
    for (int k = 0; k < 2 * HDIM; ++k)
        acc = fmaf(xs[k], W0[k * HDIM + h], acc);
    g_g[h] = acc;
}

// ---------------------------------------------------------------------------
// Kernel 1: A[m][h] = g[h] + x_m[m] @ W0[2H:3H];  B[j][h] = x_job[j] @ W0[3H:4H]
// ---------------------------------------------------------------------------
__global__ void kern_AB(const float* __restrict__ x_m,
                        const float* __restrict__ x_job,
                        const float* __restrict__ W0,
                        int M, int J)
{
    __shared__ float xs[HDIM];
    int h = threadIdx.x;
    int r = blockIdx.x;
    const float* src; const float* w; float* dst; float acc;
    if (r < M) {
        src = x_m + (size_t)r * HDIM;
        w   = W0 + (size_t)(2 * HDIM) * HDIM;
        dst = g_A + (size_t)r * HDIM;
        acc = g_g[h];
    } else {
        int j = r - M;
        src = x_job + (size_t)j * HDIM;
        w   = W0 + (size_t)(3 * HDIM) * HDIM;
        dst = g_B + (size_t)j * HDIM;
        acc = 0.0f;
    }
    xs[h] = src[h];
    __syncthreads();
    #pragma unroll 8
    for (int k = 0; k < HDIM; ++k)
        acc = fmaf(xs[k], w[k * HDIM + h], acc);
    dst[h] = acc;
}

// ---------------------------------------------------------------------------
// Kernel 1b: W1^T -> bf16 hi/lo split in blocked-SW128 layout.  Row r = output
// dim h, col c = k.  [0,32K) hi, [32K,64K) lo.
// ---------------------------------------------------------------------------
__global__ void kern_w1prep(const float* __restrict__ W1)
{
    int idx = blockIdx.x * blockDim.x + threadIdx.x;   // 0..16383
    int r = idx >> 7;
    int c = idx & 127;
    float w = W1[c * HDIM + r];
    __nv_bfloat16 hi = __float2bfloat16(w);
    __nv_bfloat16 lo = __float2bfloat16(w - __bfloat162float(hi));
    uint32_t sw = tile_off(r, c);
    *(__nv_bfloat16*)(g_W1T + sw)         = hi;
    *(__nv_bfloat16*)(g_W1T + 32768 + sw) = lo;
}

// ---------------------------------------------------------------------------
// Kernel 2: HMMA tile kernel. 128 ops/block, 256 threads (8 warps).
// Warp w computes op-rows [w*16, w*16+16) x all 128 output cols.
// D = Ahi@Whi^T + Ahi@Wlo^T + Alo@Whi^T  (fp32 accum, fixed order)
// score[op] = b2 + sum_h relu(b1[h] + D[op][h]) * W2[h]
// ---------------------------------------------------------------------------
#define OFF_AHI   0
#define OFF_ALO   32768
#define OFF_WHI   65536
#define OFF_WLO   98304
#define OFF_SB1   131072
#define OFF_SW2   131584
#define SMEM_TILE_TOTAL 132096

__global__ void __launch_bounds__(256, 1)
kern_tile(const int* __restrict__ m_ids,
          const int* __restrict__ job_idx,
          const float* __restrict__ b1,
          const float* __restrict__ W2,
          const float* __restrict__ b2,
          int n)
{
    extern __shared__ char smem[];
    uint32_t sb = smem_u32(smem);
    int tid = threadIdx.x;
    int wid = tid >> 5;
    int lid = tid & 31;
    int base = blockIdx.x * TILE_OPS;

    // ---- copy pre-swizzled W tiles (hi+lo = 64KB contiguous) ----
    {
        const uint4* src = (const uint4*)g_W1T;
        uint4* dst = (uint4*)(smem + OFF_WHI);
        #pragma unroll
        for (int i = 0; i < 16; ++i)
            dst[tid + 256 * i] = src[tid + 256 * i];
    }
    if (tid < HDIM) {
        ((float*)(smem + OFF_SB1))[tid] = b1[tid];
        ((float*)(smem + OFF_SW2))[tid] = W2[tid];
    }

    // ---- stage 1: gather h0 = relu(A[m]+B[j]), bf16 hi/lo split to smem ----
    {
        int c0 = lid * 4;                 // this lane's 4 k-columns
        uint32_t colpart = (uint32_t)(((c0 >> 6) << 4) * 1024 + (c0 & 63) * 2);
        #pragma unroll 4
        for (int i = 0; i < 16; ++i) {
            int t = wid * 16 + i;
            int op = base + t;
            int m = 0, j = 0;
            if (op < n) { m = m_ids[op]; j = job_idx[op]; }
            float4 a = *(const float4*)(g_A + m * HDIM + c0);
            float4 b = *(const float4*)(g_B + j * HDIM + c0);
            float v0 = fmaxf(a.x + b.x, 0.0f);
            float v1 = fmaxf(a.y + b.y, 0.0f);
            float v2 = fmaxf(a.z + b.z, 0.0f);
            float v3 = fmaxf(a.w + b.w, 0.0f);
            __nv_bfloat16 h0 = __float2bfloat16(v0);
            __nv_bfloat16 h1 = __float2bfloat16(v1);
            __nv_bfloat16 h2 = __float2bfloat16(v2);
            __nv_bfloat16 h3 = __float2bfloat16(v3);
            __nv_bfloat16 l0 = __float2bfloat16(v0 - __bfloat162float(h0));
            __nv_bfloat16 l1 = __float2bfloat16(v1 - __bfloat162float(h1));
            __nv_bfloat16 l2 = __float2bfloat16(v2 - __bfloat162float(h2));
            __nv_bfloat16 l3 = __float2bfloat16(v3 - __bfloat162float(h3));
            uint32_t off = colpart + (uint32_t)(((t >> 3) << 10) + (t & 7) * 128);
            uint32_t sw = off ^ ((off >> 3) & 0x70);
            uint2 phi, plo;
            phi.x = ((uint32_t)__bfloat16_as_ushort(h1) << 16) | __bfloat16_as_ushort(h0);
            phi.y = ((uint32_t)__bfloat16_as_ushort(h3) << 16) | __bfloat16_as_ushort(h2);
            plo.x = ((uint32_t)__bfloat16_as_ushort(l1) << 16) | __bfloat16_as_ushort(l0);
            plo.y = ((uint32_t)__bfloat16_as_ushort(l3) << 16) | __bfloat16_as_ushort(l2);
            *(uint2*)(smem + OFF_AHI + sw) = phi;
            *(uint2*)(smem + OFF_ALO + sw) = plo;
        }
    }
    __syncthreads();

    // ---- mainloop: 8 k-chunks x 8 n-pairs x 3 terms ----
    float d[16][4];
    #pragma unroll
    for (int nc = 0; nc < 16; ++nc)
        #pragma unroll
        for (int q = 0; q < 4; ++q) d[nc][q] = 0.0f;

    int arow = wid * 16 + (lid & 15);          // A-frag lane row
    int acolh = (lid >> 4) * 8;                // A-frag lane k-offset
    int brow_in = ((lid >> 4) << 3) + (lid & 7);   // B-frag lane n-offset within np*16
    int bcol = ((lid >> 3) & 1) * 8;           // B-frag lane k-offset

    for (int kc = 0; kc < 8; ++kc) {
        int kbase = kc * 16;
        uint32_t a_hi[4], a_lo[4];
        uint32_t aoff = tile_off(arow, kbase + acolh);
        ldsm4(a_hi, sb + OFF_AHI + aoff);
        ldsm4(a_lo, sb + OFF_ALO + aoff);
        #pragma unroll
        for (int np = 0; np < 8; ++np) {
            uint32_t b_hi[4], b_lo[4];
            uint32_t boff = tile_off(np * 16 + brow_in, kbase + bcol);
            ldsm4(b_hi, sb + OFF_WHI + boff);
            ldsm4(b_lo, sb + OFF_WLO + boff);
            mma_bf16(d[2 * np],     a_hi, b_hi[0], b_hi[1]);
            mma_bf16(d[2 * np + 1], a_hi, b_hi[2], b_hi[3]);
            mma_bf16(d[2 * np],     a_hi, b_lo[0], b_lo[1]);
            mma_bf16(d[2 * np + 1], a_hi, b_lo[2], b_lo[3]);
            mma_bf16(d[2 * np],     a_lo, b_hi[0], b_hi[1]);
            mma_bf16(d[2 * np + 1], a_lo, b_hi[2], b_hi[3]);
        }
    }

    // ---- epilogue: relu(+b1)*W2, reduce over cols ----
    // thread(g = lid>>2, t = lid&3) holds D rows (wid*16+g, +8), cols nc*8+2t,+1
    {
        const float* sb1 = (const float*)(smem + OFF_SB1);
        const float* sw2 = (const float*)(smem + OFF_SW2);
        int g = lid >> 2;
        int t = lid & 3;
        float s0 = 0.0f, s1 = 0.0f;
        #pragma unroll
        for (int nc = 0; nc < 16; ++nc) {
            int c0 = nc * 8 + 2 * t;
            float bb0 = sb1[c0], bb1 = sb1[c0 + 1];
            float w0 = sw2[c0], w1 = sw2[c0 + 1];
            s0 = fmaf(fmaxf(d[nc][0] + bb0, 0.0f), w0, s0);
            s0 = fmaf(fmaxf(d[nc][1] + bb1, 0.0f), w1, s0);
            s1 = fmaf(fmaxf(d[nc][2] + bb0, 0.0f), w0, s1);
            s1 = fmaf(fmaxf(d[nc][3] + bb1, 0.0f), w1, s1);
        }
        unsigned mask = 0xffffffffu;
        s0 += __shfl_xor_sync(mask, s0, 1);
        s0 += __shfl_xor_sync(mask, s0, 2);
        s1 += __shfl_xor_sync(mask, s1, 1);
        s1 += __shfl_xor_sync(mask, s1, 2);
        if (t == 0) {
            float bias = b2[0];
            int op0 = base + wid * 16 + g;
            int op1 = op0 + 8;
            if (op0 < n) g_scores[op0] = s0 + bias;
            if (op1 < n) g_scores[op1] = s1 + bias;
        }
    }
}

// ---------------------------------------------------------------------------
// Kernel 3a: per-block softmax partials
// ---------------------------------------------------------------------------
__global__ void __launch_bounds__(RTH)
kern_reduce1(int n, int chunk)
{
    __shared__ float  sv[RTH];
    __shared__ int    si[RTH];
    __shared__ double sz[RTH];
    __shared__ double ss[RTH];

    int tid = threadIdx.x;
    int b = blockIdx.x;
    int start = b * chunk;
    int end = min(n, start + chunk);

    float best = -INFINITY;
    int bi = 0x7fffffff;
    for (int i = start + tid; i < end; i += RTH) {
        float v = g_scores[i];
        if (v > best) { best = v; bi = i; }
    }
    sv[tid] = best; si[tid] = bi;
    __syncthreads();
    for (int s = RTH / 2; s > 0; s >>= 1) {
        if (tid < s) {
            float vo = sv[tid + s]; int io = si[tid + s];
            if (vo > sv[tid] || (vo == sv[tid] && io < si[tid])) {
                sv[tid] = vo; si[tid] = io;
            }
        }
        __syncthreads();
    }
    float mx = sv[0];
    int idx = si[0];
    __syncthreads();

    double z = 0.0, s1 = 0.0;
    for (int i = start + tid; i < end; i += RTH) {
        float t = g_scores[i] - mx;
        float e = expf(t);
        z  += (double)e;
        s1 += (double)t * (double)e;
    }
    sz[tid] = z; ss[tid] = s1;
    __syncthreads();
    for (int s = RTH / 2; s > 0; s >>= 1) {
        if (tid < s) { sz[tid] += sz[tid + s]; ss[tid] += ss[tid + s]; }
        __syncthreads();
    }
    if (tid == 0) {
        g_pmax[b] = mx;
        g_pidx[b] = idx;
        g_pZ[b]   = sz[0];
        g_pS1[b]  = ss[0];
    }
}

// ---------------------------------------------------------------------------
// Kernel 3b: combine partials (softmax-merge, fixed tree -> deterministic)
// ---------------------------------------------------------------------------
__global__ void __launch_bounds__(RBLKS)
kern_reduce2(float* __restrict__ out)
{
    __shared__ float  sv[RBLKS];
    __shared__ int    si[RBLKS];
    __shared__ double sz[RBLKS];
    __shared__ double ss[RBLKS];

    int tid = threadIdx.x;
    sv[tid] = g_pmax[tid];
    si[tid] = g_pidx[tid];
    __syncthreads();
    for (int s = RBLKS / 2; s > 0; s >>= 1) {
        if (tid < s) {
            float vo = sv[tid + s]; int io = si[tid + s];
            if (vo > sv[tid] || (vo == sv[tid] && io < si[tid])) {
                sv[tid] = vo; si[tid] = io;
            }
        }
        __syncthreads();
    }
    float mx = sv[0];
    int idx = si[0];
    __syncthreads();

    double zb = g_pZ[tid];
    double zc = 0.0, sc = 0.0;
    if (zb > 0.0) {
        double dd = (double)g_pmax[tid] - (double)mx;
        double w = exp(dd);
        zc = w * zb;
        sc = w * (g_pS1[tid] + dd * zb);
    }
    sz[tid] = zc; ss[tid] = sc;
    __syncthreads();
    for (int s = RBLKS / 2; s > 0; s >>= 1) {
        if (tid < s) { sz[tid] += sz[tid + s]; ss[tid] += ss[tid + s]; }
        __syncthreads();
    }
    if (tid == 0) {
        double Z = sz[0], S1 = ss[0];
        double logZ = log(Z);
        out[0] = (float)idx;
        out[1] = (float)(1.0 / Z);
        out[2] = (float)(-logZ);
        out[3] = (float)(logZ - S1 / Z);
    }
}

// ---------------------------------------------------------------------------
extern "C" void kernel_launch(void* const* d_in, const int* in_sizes, int n_in,
                              void* d_out, int out_size)
{
    const float* x_graph = (const float*)d_in[0];
    const float* x_m     = (const float*)d_in[1];
    const float* x_job   = (const float*)d_in[2];
    const int*   m_ids   = (const int*)  d_in[3];
    const int*   job_idx = (const int*)  d_in[4];
    const float* W0      = (const float*)d_in[5];
    const float* b0      = (const float*)d_in[6];
    const float* W1      = (const float*)d_in[7];
    const float* b1      = (const float*)d_in[8];
    const float* W2      = (const float*)d_in[9];
    const float* b2      = (const float*)d_in[10];

    int n = in_sizes[3];
    int M = in_sizes[1] / HDIM;
    int J = in_sizes[2] / HDIM;
    int chunk = (n + RBLKS - 1) / RBLKS;
    int tiles = (n + TILE_OPS - 1) / TILE_OPS;

    cudaFuncSetAttribute(kern_tile, cudaFuncAttributeMaxDynamicSharedMemorySize,
                         SMEM_TILE_TOTAL);

    kern_g<<<1, HDIM>>>(x_graph, W0, b0);
    kern_AB<<<M + J, HDIM>>>(x_m, x_job, W0, M, J);
    kern_w1prep<<<64, 256>>>(W1);
    kern_tile<<<tiles, 256, SMEM_TILE_TOTAL>>>(m_ids, job_idx, b1, W2, b2, n);
    kern_reduce1<<<RBLKS, RTH>>>(n, chunk);
    kern_reduce2<<<1, RBLKS>>>((float*)d_out);
}

// round 7
// speedup vs baseline: 6.1394x; 1.6048x over previous
#include <cuda_runtime.h>
#include <cuda_fp16.h>
#include <math.h>
#include <stdint.h>

#define HDIM 128
#define MAXM 1000
#define MAXJ 5000
#define MAXN 200000
#define TILE_OPS 128

#define RBLKS 256
#define RTH   512

// ------------------------------ scratch ------------------------------------
__device__ __align__(16) float  g_g[HDIM];
__device__ __align__(16) __half g_Ah[MAXM * HDIM];   // fp16 A rows
__device__ __align__(16) __half g_Bh[MAXJ * HDIM];   // fp16 B rows
__device__ __align__(16) float  g_scores[MAXN];
__device__ float  g_pmax[RBLKS];
__device__ int    g_pidx[RBLKS];
__device__ double g_pZ[RBLKS];
__device__ double g_pS1[RBLKS];
// W1^T (rows = output h, cols = k), fp16, blocked-SW128 layout (32KB).
__device__ __align__(16) unsigned char g_W1T[32768];

// --------------------------- helpers ---------------------------------------
__device__ __forceinline__ uint32_t smem_u32(const void* p) {
    uint32_t a;
    asm("{ .reg .u64 t; cvta.to.shared.u64 t, %1; cvt.u32.u64 %0, t; }"
        : "=r"(a) : "l"(p));
    return a;
}

// swizzled byte offset in a 128row x 128col fp16 blocked-SW128 tile
// atoms: 8 rows x 64 cols (1KB); 16 atom-rows; col-atom stride = 16KB
__device__ __forceinline__ uint32_t tile_off(int row, int col) {
    uint32_t off = (uint32_t)(((row >> 3) + ((col >> 6) << 4)) * 1024
                              + (row & 7) * 128 + (col & 63) * 2);
    return off ^ ((off >> 3) & 0x70);
}

__device__ __forceinline__ void ldsm4(uint32_t* r, uint32_t addr) {
    asm volatile("ldmatrix.sync.aligned.m8n8.x4.shared.b16 {%0,%1,%2,%3}, [%4];"
                 : "=r"(r[0]), "=r"(r[1]), "=r"(r[2]), "=r"(r[3]) : "r"(addr));
}
__device__ __forceinline__ void mma_f16(float* d, const uint32_t* a,
                                        uint32_t b0, uint32_t b1) {
    asm volatile("mma.sync.aligned.m16n8k16.row.col.f32.f16.f16.f32 "
                 "{%0,%1,%2,%3}, {%4,%5,%6,%7}, {%8,%9}, {%0,%1,%2,%3};"
                 : "+f"(d[0]), "+f"(d[1]), "+f"(d[2]), "+f"(d[3])
                 : "r"(a[0]), "r"(a[1]), "r"(a[2]), "r"(a[3]), "r"(b0), "r"(b1));
}

// ---------------------------------------------------------------------------
// Kernel 0: g[h] = b0[h] + x_graph @ W0[:2H]
// ---------------------------------------------------------------------------
__global__ void kern_g(const float* __restrict__ x_graph,
                       const float* __restrict__ W0,
                       const float* __restrict__ b0)
{
    __shared__ float xs[2 * HDIM];
    int h = threadIdx.x;
    xs[h] = x_graph[h];
    xs[h + HDIM] = x_graph[h + HDIM];
    __syncthreads();
    float acc = b0[h];
    #pragma unroll 8
    for (int k = 0; k < 2 * HDIM; ++k)
        acc = fmaf(xs[k], W0[k * HDIM + h], acc);
    g_g[h] = acc;
}

// ---------------------------------------------------------------------------
// Kernel 1: A[m][h] = g[h] + x_m[m] @ W0[2H:3H];  B[j][h] = x_job[j] @ W0[3H:4H]
// fp32 accumulate, store fp16.
// ---------------------------------------------------------------------------
__global__ void kern_AB(const float* __restrict__ x_m,
                        const float* __restrict__ x_job,
                        const float* __restrict__ W0,
                        int M, int J)
{
    __shared__ float xs[HDIM];
    int h = threadIdx.x;
    int r = blockIdx.x;
    const float* src; const float* w; __half* dst; float acc;
    if (r < M) {
        src = x_m + (size_t)r * HDIM;
        w   = W0 + (size_t)(2 * HDIM) * HDIM;
        dst = g_Ah + (size_t)r * HDIM;
        acc = g_g[h];
    } else {
        int j = r - M;
        src = x_job + (size_t)j * HDIM;
        w   = W0 + (size_t)(3 * HDIM) * HDIM;
        dst = g_Bh + (size_t)j * HDIM;
        acc = 0.0f;
    }
    xs[h] = src[h];
    __syncthreads();
    #pragma unroll 8
    for (int k = 0; k < HDIM; ++k)
        acc = fmaf(xs[k], w[k * HDIM + h], acc);
    dst[h] = __float2half(acc);
}

// ---------------------------------------------------------------------------
// Kernel 1b: W1^T -> fp16 in blocked-SW128 layout.  Row r = output h, col c = k.
// ---------------------------------------------------------------------------
__global__ void kern_w1prep(const float* __restrict__ W1)
{
    int idx = blockIdx.x * blockDim.x + threadIdx.x;   // 0..16383
    int r = idx >> 7;
    int c = idx & 127;
    float w = W1[c * HDIM + r];
    *(__half*)(g_W1T + tile_off(r, c)) = __float2half(w);
}

// ---------------------------------------------------------------------------
// Kernel 2: fp16 HMMA tile kernel. 128 ops/block, 256 threads (8 warps).
// Warp w computes op-rows [w*16, w*16+16) x all 128 output cols.
// D = h0 @ W1^T  (fp32 accum)
// score[op] = b2 + sum_h relu(b1[h] + D[op][h]) * W2[h]
// ---------------------------------------------------------------------------
#define OFF_A     0
#define OFF_W     32768
#define OFF_SB1   65536
#define OFF_SW2   66048
#define SMEM_TILE_TOTAL 66560

__global__ void __launch_bounds__(256, 2)
kern_tile(const int* __restrict__ m_ids,
          const int* __restrict__ job_idx,
          const float* __restrict__ b1,
          const float* __restrict__ W2,
          const float* __restrict__ b2,
          int n)
{
    extern __shared__ char smem[];
    uint32_t sb = smem_u32(smem);
    int tid = threadIdx.x;
    int wid = tid >> 5;
    int lid = tid & 31;
    int base = blockIdx.x * TILE_OPS;

    // ---- copy pre-swizzled W tile (32KB) ----
    {
        const uint4* src = (const uint4*)g_W1T;
        uint4* dst = (uint4*)(smem + OFF_W);
        #pragma unroll
        for (int i = 0; i < 8; ++i)
            dst[tid + 256 * i] = src[tid + 256 * i];
    }
    if (tid < HDIM) {
        ((float*)(smem + OFF_SB1))[tid] = b1[tid];
        ((float*)(smem + OFF_SW2))[tid] = W2[tid];
    }

    // ---- stage 1: gather h0 = relu(A[m]+B[j]) -> fp16 smem tile ----
    {
        int c0 = lid * 4;                 // this lane's 4 k-columns
        uint32_t colpart = (uint32_t)(((c0 >> 6) << 4) * 1024 + (c0 & 63) * 2);
        #pragma unroll 4
        for (int i = 0; i < 16; ++i) {
            int t = wid * 16 + i;
            int op = base + t;
            int m = 0, j = 0;
            if (op < n) { m = m_ids[op]; j = job_idx[op]; }
            uint2 ua = *(const uint2*)(g_Ah + m * HDIM + c0);
            uint2 ub = *(const uint2*)(g_Bh + j * HDIM + c0);
            float2 a0 = __half22float2(*(const half2*)&ua.x);
            float2 a1 = __half22float2(*(const half2*)&ua.y);
            float2 b0f = __half22float2(*(const half2*)&ub.x);
            float2 b1f = __half22float2(*(const half2*)&ub.y);
            float v0 = fmaxf(a0.x + b0f.x, 0.0f);
            float v1 = fmaxf(a0.y + b0f.y, 0.0f);
            float v2 = fmaxf(a1.x + b1f.x, 0.0f);
            float v3 = fmaxf(a1.y + b1f.y, 0.0f);
            half2 r0 = __floats2half2_rn(v0, v1);
            half2 r1 = __floats2half2_rn(v2, v3);
            uint32_t off = colpart + (uint32_t)(((t >> 3) << 10) + (t & 7) * 128);
            uint32_t sw = off ^ ((off >> 3) & 0x70);
            uint2 pv;
            pv.x = *(const uint32_t*)&r0;
            pv.y = *(const uint32_t*)&r1;
            *(uint2*)(smem + OFF_A + sw) = pv;
        }
    }
    __syncthreads();

    // ---- mainloop: 8 k-chunks x 8 n-pairs ----
    float d[16][4];
    #pragma unroll
    for (int nc = 0; nc < 16; ++nc)
        #pragma unroll
        for (int q = 0; q < 4; ++q) d[nc][q] = 0.0f;

    int arow = wid * 16 + (lid & 15);              // A-frag lane row
    int acolh = (lid >> 4) * 8;                    // A-frag lane k-offset
    int brow_in = ((lid >> 4) << 3) + (lid & 7);   // B-frag lane n-offset
    int bcol = ((lid >> 3) & 1) * 8;               // B-frag lane k-offset

    #pragma unroll
    for (int kc = 0; kc < 8; ++kc) {
        int kbase = kc * 16;
        uint32_t a[4];
        ldsm4(a, sb + OFF_A + tile_off(arow, kbase + acolh));
        #pragma unroll
        for (int np = 0; np < 8; ++np) {
            uint32_t b[4];
            ldsm4(b, sb + OFF_W + tile_off(np * 16 + brow_in, kbase + bcol));
            mma_f16(d[2 * np],     a, b[0], b[1]);
            mma_f16(d[2 * np + 1], a, b[2], b[3]);
        }
    }

    // ---- epilogue: relu(+b1)*W2, reduce over cols ----
    // thread(g = lid>>2, t = lid&3) holds D rows (wid*16+g, +8), cols nc*8+2t,+1
    {
        const float* sb1 = (const float*)(smem + OFF_SB1);
        const float* sw2 = (const float*)(smem + OFF_SW2);
        int g = lid >> 2;
        int t = lid & 3;
        float s0 = 0.0f, s1 = 0.0f;
        #pragma unroll
        for (int nc = 0; nc < 16; ++nc) {
            int c0 = nc * 8 + 2 * t;
            float bb0 = sb1[c0], bb1 = sb1[c0 + 1];
            float w0 = sw2[c0], w1 = sw2[c0 + 1];
            s0 = fmaf(fmaxf(d[nc][0] + bb0, 0.0f), w0, s0);
            s0 = fmaf(fmaxf(d[nc][1] + bb1, 0.0f), w1, s0);
            s1 = fmaf(fmaxf(d[nc][2] + bb0, 0.0f), w0, s1);
            s1 = fmaf(fmaxf(d[nc][3] + bb1, 0.0f), w1, s1);
        }
        unsigned mask = 0xffffffffu;
        s0 += __shfl_xor_sync(mask, s0, 1);
        s0 += __shfl_xor_sync(mask, s0, 2);
        s1 += __shfl_xor_sync(mask, s1, 1);
        s1 += __shfl_xor_sync(mask, s1, 2);
        if (t == 0) {
            float bias = b2[0];
            int op0 = base + wid * 16 + g;
            int op1 = op0 + 8;
            if (op0 < n) g_scores[op0] = s0 + bias;
            if (op1 < n) g_scores[op1] = s1 + bias;
        }
    }
}

// ---------------------------------------------------------------------------
// Kernel 3a: per-block softmax partials
// ---------------------------------------------------------------------------
__global__ void __launch_bounds__(RTH)
kern_reduce1(int n, int chunk)
{
    __shared__ float  sv[RTH];
    __shared__ int    si[RTH];
    __shared__ double sz[RTH];
    __shared__ double ss[RTH];

    int tid = threadIdx.x;
    int b = blockIdx.x;
    int start = b * chunk;
    int end = min(n, start + chunk);

    float best = -INFINITY;
    int bi = 0x7fffffff;
    for (int i = start + tid; i < end; i += RTH) {
        float v = g_scores[i];
        if (v > best) { best = v; bi = i; }
    }
    sv[tid] = best; si[tid] = bi;
    __syncthreads();
    for (int s = RTH / 2; s > 0; s >>= 1) {
        if (tid < s) {
            float vo = sv[tid + s]; int io = si[tid + s];
            if (vo > sv[tid] || (vo == sv[tid] && io < si[tid])) {
                sv[tid] = vo; si[tid] = io;
            }
        }
        __syncthreads();
    }
    float mx = sv[0];
    int idx = si[0];
    __syncthreads();

    double z = 0.0, s1 = 0.0;
    for (int i = start + tid; i < end; i += RTH) {
        float t = g_scores[i] - mx;
        float e = expf(t);
        z  += (double)e;
        s1 += (double)t * (double)e;
    }
    sz[tid] = z; ss[tid] = s1;
    __syncthreads();
    for (int s = RTH / 2; s > 0; s >>= 1) {
        if (tid < s) { sz[tid] += sz[tid + s]; ss[tid] += ss[tid + s]; }
        __syncthreads();
    }
    if (tid == 0) {
        g_pmax[b] = mx;
        g_pidx[b] = idx;
        g_pZ[b]   = sz[0];
        g_pS1[b]  = ss[0];
    }
}

// ---------------------------------------------------------------------------
// Kernel 3b: combine partials (softmax-merge, fixed tree -> deterministic)
// ---------------------------------------------------------------------------
__global__ void __launch_bounds__(RBLKS)
kern_reduce2(float* __restrict__ out)
{
    __shared__ float  sv[RBLKS];
    __shared__ int    si[RBLKS];
    __shared__ double sz[RBLKS];
    __shared__ double ss[RBLKS];

    int tid = threadIdx.x;
    sv[tid] = g_pmax[tid];
    si[tid] = g_pidx[tid];
    __syncthreads();
    for (int s = RBLKS / 2; s > 0; s >>= 1) {
        if (tid < s) {
            float vo = sv[tid + s]; int io = si[tid + s];
            if (vo > sv[tid] || (vo == sv[tid] && io < si[tid])) {
                sv[tid] = vo; si[tid] = io;
            }
        }
        __syncthreads();
    }
    float mx = sv[0];
    int idx = si[0];
    __syncthreads();

    double zb = g_pZ[tid];
    double zc = 0.0, sc = 0.0;
    if (zb > 0.0) {
        double dd = (double)g_pmax[tid] - (double)mx;
        double w = exp(dd);
        zc = w * zb;
        sc = w * (g_pS1[tid] + dd * zb);
    }
    sz[tid] = zc; ss[tid] = sc;
    __syncthreads();
    for (int s = RBLKS / 2; s > 0; s >>= 1) {
        if (tid < s) { sz[tid] += sz[tid + s]; ss[tid] += ss[tid + s]; }
        __syncthreads();
    }
    if (tid == 0) {
        double Z = sz[0], S1 = ss[0];
        double logZ = log(Z);
        out[0] = (float)idx;
        out[1] = (float)(1.0 / Z);
        out[2] = (float)(-logZ);
        out[3] = (float)(logZ - S1 / Z);
    }
}

// ---------------------------------------------------------------------------
extern "C" void kernel_launch(void* const* d_in, const int* in_sizes, int n_in,
                              void* d_out, int out_size)
{
    const float* x_graph = (const float*)d_in[0];
    const float* x_m     = (const float*)d_in[1];
    const float* x_job   = (const float*)d_in[2];
    const int*   m_ids   = (const int*)  d_in[3];
    const int*   job_idx = (const int*)  d_in[4];
    const float* W0      = (const float*)d_in[5];
    const float* b0      = (const float*)d_in[6];
    const float* W1      = (const float*)d_in[7];
    const float* b1      = (const float*)d_in[8];
    const float* W2      = (const float*)d_in[9];
    const float* b2      = (const float*)d_in[10];

    int n = in_sizes[3];
    int M = in_sizes[1] / HDIM;
    int J = in_sizes[2] / HDIM;
    int chunk = (n + RBLKS - 1) / RBLKS;
    int tiles = (n + TILE_OPS - 1) / TILE_OPS;

    cudaFuncSetAttribute(kern_tile, cudaFuncAttributeMaxDynamicSharedMemorySize,
                         SMEM_TILE_TOTAL);

    kern_g<<<1, HDIM>>>(x_graph, W0, b0);
    kern_AB<<<M + J, HDIM>>>(x_m, x_job, W0, M, J);
    kern_w1prep<<<64, 256>>>(W1);
    kern_tile<<<tiles, 256, SMEM_TILE_TOTAL>>>(m_ids, job_idx, b1, W2, b2, n);
    kern_reduce1<<<RBLKS, RTH>>>(n, chunk);
    kern_reduce2<<<1, RBLKS>>>((float*)d_out);
}